// round 1
// baseline (speedup 1.0000x reference)
#include <cuda_runtime.h>

typedef unsigned long long ull;

#define T_LEN   512
#define HID     50
#define NB      32          // batch rows per CTA
#define NTHREADS 256
#define HSTR    34          // padded row stride (words) for transposed h state
#define XSTR    33          // padded stride for staged x tile

// ---- shared memory layout (float offsets) ----
#define OFF_WT0 0                        // layer0 weights^T: [51][200] (row 50 = W_ih0 col, x virtual k)
#define OFF_WT1 (OFF_WT0 + 51*200)      // layer1 weights^T: [100][200] (k<50: W_ih1, k>=50: W_hh1)
#define OFF_XS  (OFF_WT1 + 100*200)     // x tile [512][33]
#define OFF_HT0 (OFF_XS  + T_LEN*XSTR)  // hT0 [51][34] (row 50 = x_t)
#define OFF_HT1 (OFF_HT0 + 51*HSTR)     // hT1 [50][34]
#define OFF_B0  (OFF_HT1 + 50*HSTR)     // bias0 [200] = b_ih0 + b_hh0
#define OFF_B1  (OFF_B0  + 200)         // bias1 [200]
#define OFF_FCW (OFF_B1  + 200)         // fc weights [64]
#define SMEM_FLOATS (OFF_FCW + 64)

// ---- packed f32x2 helpers (sm_103a FFMA2 path) ----
__device__ __forceinline__ ull pack2(float x, float y) {
    ull r; asm("mov.b64 %0, {%1, %2};" : "=l"(r) : "f"(x), "f"(y)); return r;
}
__device__ __forceinline__ void unpack2(ull v, float& x, float& y) {
    asm("mov.b64 {%0, %1}, %2;" : "=f"(x), "=f"(y) : "l"(v));
}
__device__ __forceinline__ void fma2(ull& d, ull a, ull b) {
    asm("fma.rn.f32x2 %0, %1, %2, %0;" : "+l"(d) : "l"(a), "l"(b));
}

// ---- fast activations (MUFU-based, ~1e-6 rel err; saturate correctly at +-inf) ----
__device__ __forceinline__ float sigm(float x)  { return __fdividef(1.f, 1.f + __expf(-x)); }
__device__ __forceinline__ float tanhx(float x) { return __fdividef(2.f, 1.f + __expf(-2.f*x)) - 1.f; }

// one k-step of the 200-gate matvec: 8 rows (4 pairs) x 4 gates
__device__ __forceinline__ void mv_step(ull* acc, const float* hp, const float* wp) {
    ull h2[4];
    #pragma unroll
    for (int p = 0; p < 4; ++p)
        h2[p] = *reinterpret_cast<const ull*>(hp + 2*p);
    #pragma unroll
    for (int j = 0; j < 4; ++j) {
        float w = wp[j*50];
        ull w2 = pack2(w, w);
        #pragma unroll
        for (int p = 0; p < 4; ++p)
            fma2(acc[j*4 + p], h2[p], w2);
    }
}

// unpack 16 packed gate accumulators, apply LSTM cell update, write h to smem
__device__ __forceinline__ void act_update(const ull* acc, float* cr, float* hout) {
    #pragma unroll
    for (int p = 0; p < 4; ++p) {
        float ai0, ai1, af0, af1, ag0, ag1, ao0, ao1;
        unpack2(acc[0  + p], ai0, ai1);   // i gates (j=0)
        unpack2(acc[4  + p], af0, af1);   // f gates (j=1)
        unpack2(acc[8  + p], ag0, ag1);   // g gates (j=2)
        unpack2(acc[12 + p], ao0, ao1);   // o gates (j=3)
        float c0 = sigm(af0)*cr[2*p]     + sigm(ai0)*tanhx(ag0);
        float c1 = sigm(af1)*cr[2*p + 1] + sigm(ai1)*tanhx(ag1);
        cr[2*p]     = c0;
        cr[2*p + 1] = c1;
        hout[2*p]     = sigm(ao0)*tanhx(c0);
        hout[2*p + 1] = sigm(ao1)*tanhx(c1);
    }
}

__global__ void __launch_bounds__(NTHREADS, 1)
lstm_fused_kernel(const float* __restrict__ x,
                  const float* __restrict__ Wih0, const float* __restrict__ Whh0,
                  const float* __restrict__ bih0, const float* __restrict__ bhh0,
                  const float* __restrict__ Wih1, const float* __restrict__ Whh1,
                  const float* __restrict__ bih1, const float* __restrict__ bhh1,
                  const float* __restrict__ fcw_g, const float* __restrict__ fcb_g,
                  float* __restrict__ out)
{
    extern __shared__ float sm[];
    float* Wt0 = sm + OFF_WT0;
    float* Wt1 = sm + OFF_WT1;
    float* xs  = sm + OFF_XS;
    float* hT0 = sm + OFF_HT0;
    float* hT1 = sm + OFF_HT1;
    float* bs0 = sm + OFF_B0;
    float* bs1 = sm + OFF_B1;
    float* fcw = sm + OFF_FCW;

    const int tid = threadIdx.x;
    const int b0  = blockIdx.x * NB;

    // ---- stage weights (transposed), biases, fc, x tile; zero states ----
    for (int idx = tid; idx < 51*200; idx += NTHREADS) {
        int k = idx / 200, j = idx - k*200;
        Wt0[idx] = (k < 50) ? Whh0[j*50 + k] : Wih0[j];
    }
    for (int idx = tid; idx < 100*200; idx += NTHREADS) {
        int k = idx / 200, j = idx - k*200;
        Wt1[idx] = (k < 50) ? Wih1[j*50 + k] : Whh1[j*50 + (k - 50)];
    }
    if (tid < 200) { bs0[tid] = bih0[tid] + bhh0[tid]; bs1[tid] = bih1[tid] + bhh1[tid]; }
    if (tid < HID) fcw[tid] = fcw_g[tid];
    for (int idx = tid; idx < NB*T_LEN; idx += NTHREADS) {
        int r = idx >> 9;            // T_LEN = 512
        int t = idx & (T_LEN - 1);
        xs[t*XSTR + r] = x[(size_t)(b0 + r)*T_LEN + t];   // coalesced global read
    }
    for (int idx = tid; idx < 51*HSTR; idx += NTHREADS) hT0[idx] = 0.f;
    for (int idx = tid; idx < 50*HSTR; idx += NTHREADS) hT1[idx] = 0.f;
    __syncthreads();

    const bool active = (tid < 200);
    const int  grp    = tid / 50;            // 0..3 for active threads
    const int  n      = tid - grp*50;        // hidden unit 0..49
    const int  rbase  = grp * 8;             // 8 rows per group

    float c0r[8], c1r[8];
    #pragma unroll
    for (int p = 0; p < 8; ++p) { c0r[p] = 0.f; c1r[p] = 0.f; }

    for (int t = 0; t < T_LEN; ++t) {
        // inject x_t as virtual k=50 row of layer-0 state
        if (tid < NB) hT0[50*HSTR + tid] = xs[t*XSTR + tid];
        __syncthreads();

        ull acc[16];

        // ---- layer 0: gates = bias0 + x*Wih0 + h0 @ Whh0^T   (K = 51) ----
        if (active) {
            #pragma unroll
            for (int j = 0; j < 4; ++j) {
                float b = bs0[n + 50*j];
                ull bb = pack2(b, b);
                #pragma unroll
                for (int p = 0; p < 4; ++p) acc[j*4 + p] = bb;
            }
            #pragma unroll 3
            for (int k = 0; k < 51; ++k)
                mv_step(acc, hT0 + k*HSTR + rbase, Wt0 + k*200 + n);
        }
        __syncthreads();
        if (active) act_update(acc, c0r, hT0 + n*HSTR + rbase);
        __syncthreads();

        // ---- layer 1: gates = bias1 + h0_new @ Wih1^T + h1 @ Whh1^T  (K = 100) ----
        if (active) {
            #pragma unroll
            for (int j = 0; j < 4; ++j) {
                float b = bs1[n + 50*j];
                ull bb = pack2(b, b);
                #pragma unroll
                for (int p = 0; p < 4; ++p) acc[j*4 + p] = bb;
            }
            #pragma unroll 5
            for (int k = 0; k < 50; ++k)
                mv_step(acc, hT0 + k*HSTR + rbase, Wt1 + k*200 + n);
            #pragma unroll 5
            for (int k = 0; k < 50; ++k)
                mv_step(acc, hT1 + k*HSTR + rbase, Wt1 + (k + 50)*200 + n);
        }
        __syncthreads();
        if (active) act_update(acc, c1r, hT1 + n*HSTR + rbase);
        __syncthreads();
    }

    // ---- final projection: out[b] = fc_b + fc_w . h1_final ----
    if (tid < NB) {
        float s = fcb_g[0];
        #pragma unroll
        for (int k = 0; k < HID; ++k)
            s += fcw[k] * hT1[k*HSTR + tid];
        out[b0 + tid] = s;
    }
}

extern "C" void kernel_launch(void* const* d_in, const int* in_sizes, int n_in,
                              void* d_out, int out_size)
{
    const float* x    = (const float*)d_in[0];
    const float* Wih0 = (const float*)d_in[1];
    const float* Whh0 = (const float*)d_in[2];
    const float* bih0 = (const float*)d_in[3];
    const float* bhh0 = (const float*)d_in[4];
    const float* Wih1 = (const float*)d_in[5];
    const float* Whh1 = (const float*)d_in[6];
    const float* bih1 = (const float*)d_in[7];
    const float* bhh1 = (const float*)d_in[8];
    const float* fcw  = (const float*)d_in[9];
    const float* fcb  = (const float*)d_in[10];
    float* out = (float*)d_out;

    const int B = in_sizes[0] / T_LEN;          // IN = 1
    const int grid = B / NB;                    // 4096/32 = 128 CTAs
    const size_t smem = SMEM_FLOATS * sizeof(float);   // ~199 KB

    cudaFuncSetAttribute(lstm_fused_kernel,
                         cudaFuncAttributeMaxDynamicSharedMemorySize, (int)smem);

    lstm_fused_kernel<<<grid, NTHREADS, smem>>>(
        x, Wih0, Whh0, bih0, bhh0, Wih1, Whh1, bih1, bhh1, fcw, fcb, out);
}